// round 3
// baseline (speedup 1.0000x reference)
#include <cuda_runtime.h>
#include <cstdint>

#define N_MAX 100000
#define E_MAX 1600000

// Scratch (no allocations allowed): two feature buffers + degree/norm caches.
__device__ float g_h[(size_t)N_MAX * 64];
__device__ float g_agg[(size_t)N_MAX * 64];
__device__ float g_dinv[N_MAX];
__device__ float g_norm[E_MAX];

// ---------------------------------------------------------------- degree/norm
__global__ void deg_init_k(int n) {
    int i = blockIdx.x * blockDim.x + threadIdx.x;
    if (i < n) g_dinv[i] = 1.0f;  // self-loop contributes 1 to degree
}

__global__ void deg_count_k(const int* __restrict__ dst, int E) {
    int e = blockIdx.x * blockDim.x + threadIdx.x;
    if (e < E) atomicAdd(&g_dinv[dst[e]], 1.0f);
}

__global__ void deg_fin_k(int n) {
    int i = blockIdx.x * blockDim.x + threadIdx.x;
    if (i < n) g_dinv[i] = rsqrtf(g_dinv[i]);  // deg >= 1 always
}

__global__ void norm_k(const int* __restrict__ src, const int* __restrict__ dst, int E) {
    int e = blockIdx.x * blockDim.x + threadIdx.x;
    if (e < E) g_norm[e] = g_dinv[src[e]] * g_dinv[dst[e]];
}

// ---------------------------------------------------------------- dense GEMM
// h[n, OUT] = act(x)[n, IN] @ W[IN, OUT]. W cached in shared. RELU applied to
// the *input* (fuses the previous layer's activation).
template <int IN, int OUT, bool RELU>
__global__ void gemm_k(const float* __restrict__ x, const float* __restrict__ W,
                       float* __restrict__ h, int n) {
    constexpr int NPB = 256 / OUT;  // nodes per block
    __shared__ float Ws[IN * OUT];
    for (int i = threadIdx.x; i < IN * OUT; i += 256) Ws[i] = W[i];
    __syncthreads();

    int t = threadIdx.x;
    int node = blockIdx.x * NPB + t / OUT;
    int col = t % OUT;
    if (node >= n) return;

    const float* xr = x + (size_t)node * IN;
    float acc = 0.0f;
#pragma unroll
    for (int k = 0; k < IN; k++) {
        float xv = __ldg(&xr[k]);
        if (RELU) xv = fmaxf(xv, 0.0f);
        acc += xv * Ws[k * OUT + col];
    }
    h[(size_t)node * OUT + col] = acc;
}

// ------------------------------------------------- agg init (self-loop + bias)
// agg[i,f] = dinv[i]^2 * h[i,f] + b[f]   (replaces zeroing + self-loop edges)
template <int F>
__global__ void init_agg_k(const float* __restrict__ h, const float* __restrict__ b,
                           float* __restrict__ agg, int n) {
    int idx = blockIdx.x * blockDim.x + threadIdx.x;
    if (idx >= n * F) return;
    int i = idx / F;
    int f = idx % F;
    float di = g_dinv[i];
    agg[idx] = di * di * h[idx] + b[f];
}

// ---------------------------------------------------------------- edge scatter
// One warp per edge: coalesced gather of h[src] row + coalesced RED.ADD into
// agg[dst] row.
template <int F>
__global__ void scatter_k(const float* __restrict__ h, const int* __restrict__ src,
                          const int* __restrict__ dst, float* __restrict__ agg, int E) {
    int gw = (blockIdx.x * blockDim.x + threadIdx.x) >> 5;
    int lane = threadIdx.x & 31;
    if (gw >= E) return;
    int s = __ldg(&src[gw]);
    int d = __ldg(&dst[gw]);
    float nrm = __ldg(&g_norm[gw]);
    const float* hs = h + (size_t)s * F;
    float* ad = agg + (size_t)d * F;
#pragma unroll
    for (int f = lane; f < F; f += 32) atomicAdd(&ad[f], nrm * hs[f]);
}

// F == 2 special case: thread per edge, vector gather.
__global__ void scatter2_k(const float* __restrict__ h, const int* __restrict__ src,
                           const int* __restrict__ dst, float* __restrict__ agg, int E) {
    int e = blockIdx.x * blockDim.x + threadIdx.x;
    if (e >= E) return;
    int s = __ldg(&src[e]);
    int d = __ldg(&dst[e]);
    float nrm = __ldg(&g_norm[e]);
    float2 hv = *reinterpret_cast<const float2*>(h + (size_t)s * 2);
    atomicAdd(&agg[(size_t)d * 2 + 0], nrm * hv.x);
    atomicAdd(&agg[(size_t)d * 2 + 1], nrm * hv.y);
}

static inline int cdiv(long long a, int b) { return (int)((a + b - 1) / b); }

extern "C" void kernel_launch(void* const* d_in, const int* in_sizes, int n_in,
                              void* d_out, int out_size) {
    const float* x  = (const float*)d_in[0];
    const int*   ei = (const int*)d_in[1];
    const float* W1 = (const float*)d_in[2];
    const float* b1 = (const float*)d_in[3];
    const float* W2 = (const float*)d_in[4];
    const float* b2 = (const float*)d_in[5];
    const float* W3 = (const float*)d_in[6];
    const float* b3 = (const float*)d_in[7];
    float* out = (float*)d_out;

    int n = in_sizes[0] / 64;       // 100000
    int E = in_sizes[1] / 2;        // 1600000
    const int* src = ei;
    const int* dst = ei + E;

    float *ph, *pagg;
    cudaGetSymbolAddress((void**)&ph, g_h);
    cudaGetSymbolAddress((void**)&pagg, g_agg);

    // degree + norms
    deg_init_k<<<cdiv(n, 256), 256>>>(n);
    deg_count_k<<<cdiv(E, 256), 256>>>(dst, E);
    deg_fin_k<<<cdiv(n, 256), 256>>>(n);
    norm_k<<<cdiv(E, 256), 256>>>(src, dst, E);

    // ---- layer 1: x[.,64] @ W1[64,64] -> h; agg = dinv^2 h + b1; scatter
    gemm_k<64, 64, false><<<cdiv(n, 4), 256>>>(x, W1, ph, n);
    init_agg_k<64><<<cdiv((long long)n * 64, 256), 256>>>(ph, b1, pagg, n);
    scatter_k<64><<<cdiv((long long)E * 32, 256), 256>>>(ph, src, dst, pagg, E);

    // ---- layer 2: relu(agg)[.,64] @ W2[64,32]
    gemm_k<64, 32, true><<<cdiv(n, 8), 256>>>(pagg, W2, ph, n);
    init_agg_k<32><<<cdiv((long long)n * 32, 256), 256>>>(ph, b2, pagg, n);
    scatter_k<32><<<cdiv((long long)E * 32, 256), 256>>>(ph, src, dst, pagg, E);

    // ---- layer 3: relu(agg)[.,32] @ W3[32,2] -> out directly
    gemm_k<32, 2, true><<<cdiv(n, 128), 256>>>(pagg, W3, ph, n);
    init_agg_k<2><<<cdiv((long long)n * 2, 256), 256>>>(ph, b3, out, n);
    scatter2_k<<<cdiv(E, 256), 256>>>(ph, src, dst, out, E);
}

// round 6
// speedup vs baseline: 1.5408x; 1.5408x over previous
#include <cuda_runtime.h>
#include <cstdint>

#define N_MAX 100000
#define E_MAX 1600000
#define SCAN_BS 1024
#define MAX_BLOCKS 128   // ceil(100001/1024) = 98

// Scratch (no allocations allowed)
__device__ float g_h[(size_t)N_MAX * 64];
__device__ float g_agg[(size_t)N_MAX * 64];
__device__ float g_dinv[N_MAX];
__device__ int   g_deg[N_MAX];
__device__ int   g_rowptr[N_MAX + 1];
__device__ int   g_cursor[N_MAX];
__device__ int   g_col[E_MAX];
__device__ float g_enorm[E_MAX];
__device__ int   g_bsum[MAX_BLOCKS];

// ---------------------------------------------------------------- degree
__global__ void deg_count_k(const int* __restrict__ dst, int E) {
    int e = blockIdx.x * blockDim.x + threadIdx.x;
    if (e < E) atomicAdd(&g_deg[dst[e]], 1);
}

__global__ void dinv_k(int n) {
    int i = blockIdx.x * blockDim.x + threadIdx.x;
    if (i < n) g_dinv[i] = rsqrtf((float)(g_deg[i] + 1));  // +1 self-loop
}

// ---------------------------------------------------------------- CSR build
// Two-level exclusive scan over degrees -> rowptr.
__global__ void scan_block_k(int n) {
    __shared__ int sh[SCAN_BS];
    int i = blockIdx.x * SCAN_BS + threadIdx.x;
    int v = (i < n) ? g_deg[i] : 0;
    sh[threadIdx.x] = v;
    __syncthreads();
    for (int off = 1; off < SCAN_BS; off <<= 1) {
        int t = (threadIdx.x >= off) ? sh[threadIdx.x - off] : 0;
        __syncthreads();
        sh[threadIdx.x] += t;
        __syncthreads();
    }
    if (i < n) g_rowptr[i] = sh[threadIdx.x] - v;  // exclusive
    if (threadIdx.x == SCAN_BS - 1) g_bsum[blockIdx.x] = sh[SCAN_BS - 1];
}

__global__ void scan_sums_k(int nb) {
    if (threadIdx.x == 0) {
        int acc = 0;
        for (int b = 0; b < nb; b++) { int t = g_bsum[b]; g_bsum[b] = acc; acc += t; }
    }
}

__global__ void add_off_k(int n, int E) {
    int i = blockIdx.x * SCAN_BS + threadIdx.x;
    if (i < n) g_rowptr[i] += g_bsum[blockIdx.x];
    if (i == 0) g_rowptr[n] = E;
}

// Place each edge into its dst row; store src index + edge norm.
__global__ void place_k(const int* __restrict__ src, const int* __restrict__ dst, int E) {
    int e = blockIdx.x * blockDim.x + threadIdx.x;
    if (e >= E) return;
    int s = src[e], d = dst[e];
    int pos = g_rowptr[d] + atomicAdd(&g_cursor[d], 1);
    g_col[pos] = s;
    g_enorm[pos] = g_dinv[s] * g_dinv[d];
}

// ---------------------------------------------------------------- dense GEMM
template <int IN, int OUT, bool RELU>
__global__ void gemm_k(const float* __restrict__ x, const float* __restrict__ W,
                       float* __restrict__ h, int n) {
    constexpr int NPB = 256 / OUT;
    __shared__ float Ws[IN * OUT];
    for (int i = threadIdx.x; i < IN * OUT; i += 256) Ws[i] = W[i];
    __syncthreads();

    int t = threadIdx.x;
    int node = blockIdx.x * NPB + t / OUT;
    int col = t % OUT;
    if (node >= n) return;

    const float* xr = x + (size_t)node * IN;
    float acc = 0.0f;
#pragma unroll
    for (int k = 0; k < IN; k++) {
        float xv = __ldg(&xr[k]);
        if (RELU) xv = fmaxf(xv, 0.0f);
        acc += xv * Ws[k * OUT + col];
    }
    h[(size_t)node * OUT + col] = acc;
}

// ------------------------------------------------ pull-mode aggregation
// One warp per dst node. Accumulator initialized with self-loop + bias;
// then sum norm[e] * h[col[e]] over the CSR row. No atomics.
// F == 64: each lane owns features (lane, lane+32).
__global__ void aggregate64_k(const float* __restrict__ h, const float* __restrict__ b,
                              float* __restrict__ agg, int n) {
    int node = (blockIdx.x * blockDim.x + threadIdx.x) >> 5;
    int lane = threadIdx.x & 31;
    if (node >= n) return;
    float di = g_dinv[node];
    float sl = di * di;
    const float* hr = h + (size_t)node * 64;
    float a0 = sl * hr[lane]      + b[lane];
    float a1 = sl * hr[lane + 32] + b[lane + 32];
    int beg = g_rowptr[node], end = g_rowptr[node + 1];
    int e = beg;
    for (; e + 1 < end; e += 2) {      // 2-edge unroll for MLP
        int s0 = g_col[e],     s1 = g_col[e + 1];
        float w0 = g_enorm[e], w1 = g_enorm[e + 1];
        const float* h0 = h + (size_t)s0 * 64;
        const float* h1 = h + (size_t)s1 * 64;
        float v00 = h0[lane], v01 = h0[lane + 32];
        float v10 = h1[lane], v11 = h1[lane + 32];
        a0 += w0 * v00 + w1 * v10;
        a1 += w0 * v01 + w1 * v11;
    }
    if (e < end) {
        int s = g_col[e]; float w = g_enorm[e];
        const float* hs = h + (size_t)s * 64;
        a0 += w * hs[lane];
        a1 += w * hs[lane + 32];
    }
    agg[(size_t)node * 64 + lane]      = a0;
    agg[(size_t)node * 64 + lane + 32] = a1;
}

// F == 32: one feature per lane.
__global__ void aggregate32_k(const float* __restrict__ h, const float* __restrict__ b,
                              float* __restrict__ agg, int n) {
    int node = (blockIdx.x * blockDim.x + threadIdx.x) >> 5;
    int lane = threadIdx.x & 31;
    if (node >= n) return;
    float di = g_dinv[node];
    float a0 = di * di * h[(size_t)node * 32 + lane] + b[lane];
    int beg = g_rowptr[node], end = g_rowptr[node + 1];
    int e = beg;
    for (; e + 1 < end; e += 2) {
        int s0 = g_col[e],     s1 = g_col[e + 1];
        float w0 = g_enorm[e], w1 = g_enorm[e + 1];
        float v0 = h[(size_t)s0 * 32 + lane];
        float v1 = h[(size_t)s1 * 32 + lane];
        a0 += w0 * v0 + w1 * v1;
    }
    if (e < end) a0 += g_enorm[e] * h[(size_t)g_col[e] * 32 + lane];
    agg[(size_t)node * 32 + lane] = a0;
}

// F == 2: one warp per node, lanes strided over edges, butterfly reduce.
__global__ void aggregate2_k(const float* __restrict__ h, const float* __restrict__ b,
                             float* __restrict__ agg, int n) {
    int node = (blockIdx.x * blockDim.x + threadIdx.x) >> 5;
    int lane = threadIdx.x & 31;
    if (node >= n) return;
    int beg = g_rowptr[node], end = g_rowptr[node + 1];
    float ax = 0.0f, ay = 0.0f;
    for (int e = beg + lane; e < end; e += 32) {
        int s = g_col[e]; float w = g_enorm[e];
        float2 hv = *reinterpret_cast<const float2*>(h + (size_t)s * 2);
        ax += w * hv.x;
        ay += w * hv.y;
    }
#pragma unroll
    for (int off = 16; off; off >>= 1) {
        ax += __shfl_xor_sync(0xffffffffu, ax, off);
        ay += __shfl_xor_sync(0xffffffffu, ay, off);
    }
    if (lane == 0) {
        float di = g_dinv[node], sl = di * di;
        float2 hv = *reinterpret_cast<const float2*>(h + (size_t)node * 2);
        agg[(size_t)node * 2 + 0] = ax + sl * hv.x + b[0];
        agg[(size_t)node * 2 + 1] = ay + sl * hv.y + b[1];
    }
}

static inline int cdiv(long long a, int b) { return (int)((a + b - 1) / b); }

extern "C" void kernel_launch(void* const* d_in, const int* in_sizes, int n_in,
                              void* d_out, int out_size) {
    const float* x  = (const float*)d_in[0];
    const int*   ei = (const int*)d_in[1];
    const float* W1 = (const float*)d_in[2];
    const float* b1 = (const float*)d_in[3];
    const float* W2 = (const float*)d_in[4];
    const float* b2 = (const float*)d_in[5];
    const float* W3 = (const float*)d_in[6];
    const float* b3 = (const float*)d_in[7];
    float* out = (float*)d_out;

    int n = in_sizes[0] / 64;   // 100000
    int E = in_sizes[1] / 2;    // 1600000
    const int* src = ei;
    const int* dst = ei + E;

    float *ph, *pagg;
    void *pdeg, *pcur;
    cudaGetSymbolAddress((void**)&ph, g_h);
    cudaGetSymbolAddress((void**)&pagg, g_agg);
    cudaGetSymbolAddress(&pdeg, g_deg);
    cudaGetSymbolAddress(&pcur, g_cursor);

    int nb = cdiv(n, SCAN_BS);

    // ---- CSR build + norms
    cudaMemsetAsync(pdeg, 0, n * sizeof(int));
    cudaMemsetAsync(pcur, 0, n * sizeof(int));
    deg_count_k<<<cdiv(E, 256), 256>>>(dst, E);
    dinv_k<<<cdiv(n, 256), 256>>>(n);
    scan_block_k<<<nb, SCAN_BS>>>(n);
    scan_sums_k<<<1, 32>>>(nb);
    add_off_k<<<nb, SCAN_BS>>>(n, E);
    place_k<<<cdiv(E, 256), 256>>>(src, dst, E);

    // ---- layer 1: h = x @ W1 ; agg = A_hat h + b1
    gemm_k<64, 64, false><<<cdiv(n, 4), 256>>>(x, W1, ph, n);
    aggregate64_k<<<cdiv((long long)n * 32, 256), 256>>>(ph, b1, pagg, n);

    // ---- layer 2: h = relu(agg) @ W2 ; agg = A_hat h + b2
    gemm_k<64, 32, true><<<cdiv(n, 8), 256>>>(pagg, W2, ph, n);
    aggregate32_k<<<cdiv((long long)n * 32, 256), 256>>>(ph, b2, pagg, n);

    // ---- layer 3: h = relu(agg) @ W3 ; out = A_hat h + b3
    gemm_k<32, 2, true><<<cdiv(n, 128), 256>>>(pagg, W3, ph, n);
    aggregate2_k<<<cdiv((long long)n * 32, 256), 256>>>(ph, b3, out, n);
}

// round 8
// speedup vs baseline: 2.0917x; 1.3576x over previous
#include <cuda_runtime.h>
#include <cstdint>

#define N_MAX 100000
#define E_MAX 1600000
#define SCAN_BS 1024
#define MAX_BLOCKS 128

// Scratch (no allocations allowed)
__device__ float g_h[(size_t)N_MAX * 64];
__device__ float g_agg[(size_t)N_MAX * 64];
__device__ float g_dinv[N_MAX];
__device__ int   g_deg[N_MAX];
__device__ int   g_rowptr[N_MAX + 1];
__device__ int   g_cursor[N_MAX];
__device__ int2  g_edge[E_MAX];     // {src_col, norm_as_int}
__device__ int   g_bsum[MAX_BLOCKS];

static inline int cdiv(long long a, int b) { return (int)((a + b - 1) / b); }

// ---------------------------------------------------------------- degree
__global__ void deg_count_k(const int* __restrict__ dst, int E) {
    int e = blockIdx.x * blockDim.x + threadIdx.x;
    if (e < E) atomicAdd(&g_deg[dst[e]], 1);
}

// ---------------------------------------------------------------- CSR build
// Block-level exclusive scan over degrees; also computes dinv (reads deg anyway).
__global__ void scan_block_k(int n) {
    __shared__ int sh[SCAN_BS];
    int i = blockIdx.x * SCAN_BS + threadIdx.x;
    int v = (i < n) ? g_deg[i] : 0;
    if (i < n) g_dinv[i] = rsqrtf((float)(v + 1));  // +1 self-loop
    sh[threadIdx.x] = v;
    __syncthreads();
    for (int off = 1; off < SCAN_BS; off <<= 1) {
        int t = (threadIdx.x >= off) ? sh[threadIdx.x - off] : 0;
        __syncthreads();
        sh[threadIdx.x] += t;
        __syncthreads();
    }
    if (i < n) g_rowptr[i] = sh[threadIdx.x] - v;  // exclusive
    if (threadIdx.x == SCAN_BS - 1) g_bsum[blockIdx.x] = sh[SCAN_BS - 1];
}

// Parallel scan of per-block sums (nb <= 98): one block of 128 threads.
__global__ void scan_sums_k(int nb) {
    int t = threadIdx.x;                 // 128 threads
    int lane = t & 31, w = t >> 5;
    int v = (t < nb) ? g_bsum[t] : 0;
    int s = v;
#pragma unroll
    for (int off = 1; off < 32; off <<= 1) {
        int u = __shfl_up_sync(0xffffffffu, s, off);
        if (lane >= off) s += u;
    }
    __shared__ int wsum[4];
    if (lane == 31) wsum[w] = s;
    __syncthreads();
    int base = 0;
    for (int i = 0; i < w; i++) base += wsum[i];
    if (t < nb) g_bsum[t] = base + s - v;  // exclusive
}

__global__ void add_off_k(int n, int E) {
    int i = blockIdx.x * SCAN_BS + threadIdx.x;
    if (i < n) g_rowptr[i] += g_bsum[blockIdx.x];
    if (i == 0) g_rowptr[n] = E;
}

__global__ void place_k(const int* __restrict__ src, const int* __restrict__ dst, int E) {
    int e = blockIdx.x * blockDim.x + threadIdx.x;
    if (e >= E) return;
    int s = src[e], d = dst[e];
    int pos = g_rowptr[d] + atomicAdd(&g_cursor[d], 1);
    int2 pk;
    pk.x = s;
    pk.y = __float_as_int(g_dinv[s] * g_dinv[d]);
    g_edge[pos] = pk;
}

// ---------------------------------------------------------------- GEMMs
// 64->64: 2 warps per node (warp half = cols [half*32, half*32+32)).
// W column kept in 64 registers/thread; x row loaded once coalesced (float2/lane)
// and broadcast via shuffles. Block = 256 thr = 8 warps = 4 nodes/iter, 8 iters.
template <bool RELU>
__global__ __launch_bounds__(256) void gemm64x64_k(
    const float* __restrict__ x, const float* __restrict__ W,
    float* __restrict__ h, int n) {
    int w = threadIdx.x >> 5, lane = threadIdx.x & 31;
    int half = w & 1;
    int col = half * 32 + lane;

    float wr[64];
#pragma unroll
    for (int k = 0; k < 64; k++) wr[k] = __ldg(&W[k * 64 + col]);

    int base = blockIdx.x * 32;
#pragma unroll 1
    for (int it = 0; it < 8; it++) {
        int node = base + it * 4 + (w >> 1);
        if (node >= n) return;
        float2 xv = *reinterpret_cast<const float2*>(x + (size_t)node * 64 + lane * 2);
        if (RELU) { xv.x = fmaxf(xv.x, 0.0f); xv.y = fmaxf(xv.y, 0.0f); }
        float acc = 0.0f;
#pragma unroll
        for (int j = 0; j < 32; j++) {
            float xx = __shfl_sync(0xffffffffu, xv.x, j);
            float xy = __shfl_sync(0xffffffffu, xv.y, j);
            acc += xx * wr[2 * j] + xy * wr[2 * j + 1];
        }
        h[(size_t)node * 64 + col] = acc;
    }
}

// 64->32 (relu input): 1 warp per node, col = lane. Block = 8 nodes/iter, 8 iters.
__global__ __launch_bounds__(256) void gemm64x32_k(
    const float* __restrict__ x, const float* __restrict__ W,
    float* __restrict__ h, int n) {
    int w = threadIdx.x >> 5, lane = threadIdx.x & 31;

    float wr[64];
#pragma unroll
    for (int k = 0; k < 64; k++) wr[k] = __ldg(&W[k * 32 + lane]);

    int base = blockIdx.x * 64;
#pragma unroll 1
    for (int it = 0; it < 8; it++) {
        int node = base + it * 8 + w;
        if (node >= n) return;
        float2 xv = *reinterpret_cast<const float2*>(x + (size_t)node * 64 + lane * 2);
        xv.x = fmaxf(xv.x, 0.0f);
        xv.y = fmaxf(xv.y, 0.0f);
        float acc = 0.0f;
#pragma unroll
        for (int j = 0; j < 32; j++) {
            float xx = __shfl_sync(0xffffffffu, xv.x, j);
            float xy = __shfl_sync(0xffffffffu, xv.y, j);
            acc += xx * wr[2 * j] + xy * wr[2 * j + 1];
        }
        h[(size_t)node * 32 + lane] = acc;
    }
}

// 32->2 (relu input): warp per node, lane owns one k, butterfly reduce 2 outputs.
__global__ void gemm32x2_k(const float* __restrict__ x, const float* __restrict__ W,
                           float* __restrict__ h, int n) {
    int node = (blockIdx.x * blockDim.x + threadIdx.x) >> 5;
    int lane = threadIdx.x & 31;
    if (node >= n) return;
    float xv = fmaxf(x[(size_t)node * 32 + lane], 0.0f);
    float p0 = xv * __ldg(&W[lane * 2 + 0]);
    float p1 = xv * __ldg(&W[lane * 2 + 1]);
#pragma unroll
    for (int off = 16; off; off >>= 1) {
        p0 += __shfl_xor_sync(0xffffffffu, p0, off);
        p1 += __shfl_xor_sync(0xffffffffu, p1, off);
    }
    if (lane == 0) {
        h[(size_t)node * 2 + 0] = p0;
        h[(size_t)node * 2 + 1] = p1;
    }
}

// ------------------------------------------------ pull-mode aggregation
__global__ void aggregate64_k(const float* __restrict__ h, const float* __restrict__ b,
                              float* __restrict__ agg, int n) {
    int node = (blockIdx.x * blockDim.x + threadIdx.x) >> 5;
    int lane = threadIdx.x & 31;
    if (node >= n) return;
    float di = g_dinv[node];
    float sl = di * di;
    const float* hr = h + (size_t)node * 64;
    float a0 = sl * hr[lane]      + b[lane];
    float a1 = sl * hr[lane + 32] + b[lane + 32];
    int beg = g_rowptr[node], end = g_rowptr[node + 1];
    int e = beg;
    for (; e + 1 < end; e += 2) {
        int2 e0 = g_edge[e], e1 = g_edge[e + 1];
        float w0 = __int_as_float(e0.y), w1 = __int_as_float(e1.y);
        const float* h0 = h + (size_t)e0.x * 64;
        const float* h1 = h + (size_t)e1.x * 64;
        float v00 = h0[lane], v01 = h0[lane + 32];
        float v10 = h1[lane], v11 = h1[lane + 32];
        a0 += w0 * v00 + w1 * v10;
        a1 += w0 * v01 + w1 * v11;
    }
    if (e < end) {
        int2 e0 = g_edge[e];
        float w = __int_as_float(e0.y);
        const float* hs = h + (size_t)e0.x * 64;
        a0 += w * hs[lane];
        a1 += w * hs[lane + 32];
    }
    agg[(size_t)node * 64 + lane]      = a0;
    agg[(size_t)node * 64 + lane + 32] = a1;
}

__global__ void aggregate32_k(const float* __restrict__ h, const float* __restrict__ b,
                              float* __restrict__ agg, int n) {
    int node = (blockIdx.x * blockDim.x + threadIdx.x) >> 5;
    int lane = threadIdx.x & 31;
    if (node >= n) return;
    float di = g_dinv[node];
    float a0 = di * di * h[(size_t)node * 32 + lane] + b[lane];
    int beg = g_rowptr[node], end = g_rowptr[node + 1];
    int e = beg;
    for (; e + 1 < end; e += 2) {
        int2 e0 = g_edge[e], e1 = g_edge[e + 1];
        float w0 = __int_as_float(e0.y), w1 = __int_as_float(e1.y);
        float v0 = h[(size_t)e0.x * 32 + lane];
        float v1 = h[(size_t)e1.x * 32 + lane];
        a0 += w0 * v0 + w1 * v1;
    }
    if (e < end) {
        int2 e0 = g_edge[e];
        a0 += __int_as_float(e0.y) * h[(size_t)e0.x * 32 + lane];
    }
    agg[(size_t)node * 32 + lane] = a0;
}

__global__ void aggregate2_k(const float* __restrict__ h, const float* __restrict__ b,
                             float* __restrict__ agg, int n) {
    int node = (blockIdx.x * blockDim.x + threadIdx.x) >> 5;
    int lane = threadIdx.x & 31;
    if (node >= n) return;
    int beg = g_rowptr[node], end = g_rowptr[node + 1];
    float ax = 0.0f, ay = 0.0f;
    for (int e = beg + lane; e < end; e += 32) {
        int2 e0 = g_edge[e];
        float w = __int_as_float(e0.y);
        float2 hv = *reinterpret_cast<const float2*>(h + (size_t)e0.x * 2);
        ax += w * hv.x;
        ay += w * hv.y;
    }
#pragma unroll
    for (int off = 16; off; off >>= 1) {
        ax += __shfl_xor_sync(0xffffffffu, ax, off);
        ay += __shfl_xor_sync(0xffffffffu, ay, off);
    }
    if (lane == 0) {
        float di = g_dinv[node], sl = di * di;
        float2 hv = *reinterpret_cast<const float2*>(h + (size_t)node * 2);
        agg[(size_t)node * 2 + 0] = ax + sl * hv.x + b[0];
        agg[(size_t)node * 2 + 1] = ay + sl * hv.y + b[1];
    }
}

extern "C" void kernel_launch(void* const* d_in, const int* in_sizes, int n_in,
                              void* d_out, int out_size) {
    const float* x  = (const float*)d_in[0];
    const int*   ei = (const int*)d_in[1];
    const float* W1 = (const float*)d_in[2];
    const float* b1 = (const float*)d_in[3];
    const float* W2 = (const float*)d_in[4];
    const float* b2 = (const float*)d_in[5];
    const float* W3 = (const float*)d_in[6];
    const float* b3 = (const float*)d_in[7];
    float* out = (float*)d_out;

    int n = in_sizes[0] / 64;   // 100000
    int E = in_sizes[1] / 2;    // 1600000
    const int* src = ei;
    const int* dst = ei + E;

    float *ph, *pagg;
    void *pdeg, *pcur;
    cudaGetSymbolAddress((void**)&ph, g_h);
    cudaGetSymbolAddress((void**)&pagg, g_agg);
    cudaGetSymbolAddress(&pdeg, g_deg);
    cudaGetSymbolAddress(&pcur, g_cursor);

    int nb = cdiv(n, SCAN_BS);

    // ---- CSR build + norms
    cudaMemsetAsync(pdeg, 0, n * sizeof(int));
    cudaMemsetAsync(pcur, 0, n * sizeof(int));
    deg_count_k<<<cdiv(E, 256), 256>>>(dst, E);
    scan_block_k<<<nb, SCAN_BS>>>(n);      // also computes dinv
    scan_sums_k<<<1, 128>>>(nb);
    add_off_k<<<nb, SCAN_BS>>>(n, E);
    place_k<<<cdiv(E, 256), 256>>>(src, dst, E);

    // ---- layer 1
    gemm64x64_k<false><<<cdiv(n, 32), 256>>>(x, W1, ph, n);
    aggregate64_k<<<cdiv((long long)n * 32, 256), 256>>>(ph, b1, pagg, n);

    // ---- layer 2
    gemm64x32_k<<<cdiv(n, 64), 256>>>(pagg, W2, ph, n);
    aggregate32_k<<<cdiv((long long)n * 32, 256), 256>>>(ph, b2, pagg, n);

    // ---- layer 3
    gemm32x2_k<<<cdiv((long long)n * 32, 256), 256>>>(pagg, W3, ph, n);
    aggregate2_k<<<cdiv((long long)n * 32, 256), 256>>>(ph, b3, out, n);
}